// round 15
// baseline (speedup 1.0000x reference)
#include <cuda_runtime.h>

// PositionEmbeddingEncoder (R11) — wavefront-minimized mapping
//  + smem x-staging + smem-resident w1/w2.
// lane t: point = pair*2 + (t>>4), depth = ((t>>1)&7)+1, half = t&1.
// Gather: lanes 2k,2k+1 read the two 16B halves of the SAME 32B table row.
//   Depth 1-2 lanes (8/32) read from a block-staged smem copy of w1+w2
//   (2.25KB) -> global gather LDG has 24 lanes / 12 lines (was 16 lines).
// Store: (lane&15)*16B within the 256B point row -> 4 lines per STG.128.
// U=4 + (256,8) bounds keep regs<=32 -> 64 warps/SM (occupancy is the
// latency-hiding mechanism; R4 showed bigger U regresses via regs).

#define HALF_SIZE  128.0f
#define U          4
#define WARPS_PB   8
#define PTS_PB     (WARPS_PB * U * 2)   // 64 points per block
#define W12_FLOATS (64 + 512)           // w1: 8*8, w2: 64*8

__global__ __launch_bounds__(256, 8)
void pee_kernel(const float* __restrict__ x,
                const float* __restrict__ w1,
                const float* __restrict__ w2,
                const float* __restrict__ w3,
                const float* __restrict__ w4,
                const float* __restrict__ w5,
                const float* __restrict__ w6,
                const float* __restrict__ w7,
                const float* __restrict__ w8,
                float* __restrict__ out,
                int n)
{
    __shared__ float xs[PTS_PB * 3];                      // 768 B
    __shared__ __align__(16) float wlo[W12_FLOATS];       // 2304 B

    const int tid  = threadIdx.x;
    const int lane = tid & 31;
    const int warp = tid >> 5;

    // ---- cooperative staging: x (coalesced) + w1/w2 (L2-hit, coalesced) ----
    {
        int base = blockIdx.x * (PTS_PB * 3);
        if (tid < PTS_PB * 3) {
            int gidx = base + tid;
            xs[tid] = (gidx < n * 3) ? x[gidx] : 0.0f;
        }
        for (int i = tid; i < W12_FLOATS; i += 256)
            wlo[i] = (i < 64) ? __ldg(&w1[i]) : __ldg(&w2[i - 64]);
    }
    __syncthreads();

    const int dm = (lane >> 1) & 7;       // 0..7 -> depth = dm+1
    const int h  = lane & 1;              // row half
    const int ps = lane >> 4;             // point-of-pair

    const bool lo = (dm <= 1);            // w1/w2: serve from smem
    const int  lobase = (dm == 1) ? 64 : 0;

    const float* wp;
    switch (dm) {
        case 0: wp = w1; break;           // unused when lo, kept for safety
        case 1: wp = w2; break;
        case 2: wp = w3; break;
        case 3: wp = w4; break;
        case 4: wp = w5; break;
        case 5: wp = w6; break;
        case 6: wp = w7; break;
        default: wp = w8; break;
    }

    const int   depth = dm + 1;
    const int   g     = 1 << depth;
    // (x+128) * (g/256): both scalings exact powers of two -> bit-identical
    // to ((x+128)/256)*g as computed by the reference.
    const float kf    = (float)g * (1.0f / 256.0f);

    const int lp0     = warp * (U * 2) + ps;
    const int pt_base = blockIdx.x * PTS_PB + lp0;

    float4 v[U];

#pragma unroll
    for (int u = 0; u < U; u++) {
        int lp = lp0 + u * 2;
        int pt = pt_base + u * 2;
        if (pt < n) {
            float fx = (xs[lp * 3 + 0] + HALF_SIZE) * kf;
            float fy = (xs[lp * 3 + 1] + HALF_SIZE) * kf;
            float fz = (xs[lp * 3 + 2] + HALF_SIZE) * kf;

            int gx = min(max(__float2int_rd(fx), 0), g - 1);
            int gy = min(max(__float2int_rd(fy), 0), g - 1);
            int gz = min(max(__float2int_rd(fz), 0), g - 1);

            unsigned int flat = (unsigned int)gx
                              + ((unsigned int)gy << depth)
                              + ((unsigned int)gz << (2 * depth));

            unsigned int off = flat * 8u + (unsigned int)h * 4u;
            if (lo)
                v[u] = *(const float4*)&wlo[lobase + off];   // LDS.128
            else
                v[u] = __ldg((const float4*)(wp + (size_t)off));
        }
    }

#pragma unroll
    for (int u = 0; u < U; u++) {
        int pt = pt_base + u * 2;
        if (pt < n) {
            __stcs((float4*)(out + (size_t)pt * 64) + (lane & 15), v[u]);
        }
    }
}

extern "C" void kernel_launch(void* const* d_in, const int* in_sizes, int n_in,
                              void* d_out, int out_size)
{
    const float* x  = (const float*)d_in[0];
    const float* w1 = (const float*)d_in[1];
    const float* w2 = (const float*)d_in[2];
    const float* w3 = (const float*)d_in[3];
    const float* w4 = (const float*)d_in[4];
    const float* w5 = (const float*)d_in[5];
    const float* w6 = (const float*)d_in[6];
    const float* w7 = (const float*)d_in[7];
    const float* w8 = (const float*)d_in[8];
    float* out = (float*)d_out;

    int n = in_sizes[0] / 3;

    int blocks = (n + PTS_PB - 1) / PTS_PB;
    pee_kernel<<<blocks, 256>>>(x, w1, w2, w3, w4, w5, w6, w7, w8, out, n);
}

// round 17
// speedup vs baseline: 1.1793x; 1.1793x over previous
#include <cuda_runtime.h>

// PositionEmbeddingEncoder (R12) — R10 shape (best: 84.0us) + exact-size
// fast path (n % 64 == 0 -> no bounds checks).
// lane t: point = pair*2 + (t>>4), depth = ((t>>1)&7)+1, half = t&1.
// Gather: lanes 2k,2k+1 read the two 16B halves of the SAME 32B table row
//   -> 16 distinct 128B lines per LDG.128 (maximal line sharing for random rows).
// Store: (lane&15)*16B within the 256B point row -> 4 lines per STG.128.
// x: block-cooperatively staged into smem (coalesced).
// U=4 + (256,8) bounds keep regs<=32 -> 64 warps/SM (occupancy hides the
// ~600cyc random-gather latency; R4/R11 showed both bigger U and hybrid
// LDS paths regress).

#define HALF_SIZE  128.0f
#define U          4
#define WARPS_PB   8
#define PTS_PB     (WARPS_PB * U * 2)   // 64 points per block

template<bool CHECK>
__global__ __launch_bounds__(256, 8)
void pee_kernel(const float* __restrict__ x,
                const float* __restrict__ w1,
                const float* __restrict__ w2,
                const float* __restrict__ w3,
                const float* __restrict__ w4,
                const float* __restrict__ w5,
                const float* __restrict__ w6,
                const float* __restrict__ w7,
                const float* __restrict__ w8,
                float* __restrict__ out,
                int n)
{
    __shared__ float xs[PTS_PB * 3];     // 768 B

    const int tid  = threadIdx.x;
    const int lane = tid & 31;
    const int warp = tid >> 5;

    // ---- cooperative, coalesced x staging ----
    {
        int base = blockIdx.x * (PTS_PB * 3);
        if (tid < PTS_PB * 3) {
            int gidx = base + tid;
            if (CHECK)
                xs[tid] = (gidx < n * 3) ? x[gidx] : 0.0f;
            else
                xs[tid] = x[gidx];
        }
    }
    __syncthreads();

    const int dm = (lane >> 1) & 7;       // 0..7 -> depth = dm+1
    const int h  = lane & 1;              // row half
    const int ps = lane >> 4;             // point-of-pair

    const float* wp;
    switch (dm) {
        case 0: wp = w1; break;
        case 1: wp = w2; break;
        case 2: wp = w3; break;
        case 3: wp = w4; break;
        case 4: wp = w5; break;
        case 5: wp = w6; break;
        case 6: wp = w7; break;
        default: wp = w8; break;
    }

    const int   depth = dm + 1;
    const int   g     = 1 << depth;
    // (x+128) * (g/256): both scalings are exact powers of two, so this is
    // bit-identical to ((x+128)/256)*g as computed by the reference.
    const float kf    = (float)g * (1.0f / 256.0f);

    const int lp0     = warp * (U * 2) + ps;
    const int pt_base = blockIdx.x * PTS_PB + lp0;

    float4 v[U];

#pragma unroll
    for (int u = 0; u < U; u++) {
        int lp = lp0 + u * 2;
        if (!CHECK || (pt_base + u * 2) < n) {
            float fx = (xs[lp * 3 + 0] + HALF_SIZE) * kf;
            float fy = (xs[lp * 3 + 1] + HALF_SIZE) * kf;
            float fz = (xs[lp * 3 + 2] + HALF_SIZE) * kf;

            int gx = min(max(__float2int_rd(fx), 0), g - 1);
            int gy = min(max(__float2int_rd(fy), 0), g - 1);
            int gz = min(max(__float2int_rd(fz), 0), g - 1);

            unsigned int flat = (unsigned int)gx
                              + ((unsigned int)gy << depth)
                              + ((unsigned int)gz << (2 * depth));

            v[u] = __ldg((const float4*)(wp + (size_t)flat * 8u + (unsigned)h * 4u));
        }
    }

#pragma unroll
    for (int u = 0; u < U; u++) {
        int pt = pt_base + u * 2;
        if (!CHECK || pt < n) {
            __stcs((float4*)(out + (size_t)pt * 64) + (lane & 15), v[u]);
        }
    }
}

extern "C" void kernel_launch(void* const* d_in, const int* in_sizes, int n_in,
                              void* d_out, int out_size)
{
    const float* x  = (const float*)d_in[0];
    const float* w1 = (const float*)d_in[1];
    const float* w2 = (const float*)d_in[2];
    const float* w3 = (const float*)d_in[3];
    const float* w4 = (const float*)d_in[4];
    const float* w5 = (const float*)d_in[5];
    const float* w6 = (const float*)d_in[6];
    const float* w7 = (const float*)d_in[7];
    const float* w8 = (const float*)d_in[8];
    float* out = (float*)d_out;

    int n = in_sizes[0] / 3;
    int blocks = (n + PTS_PB - 1) / PTS_PB;

    if (n % PTS_PB == 0) {
        pee_kernel<false><<<blocks, 256>>>(x, w1, w2, w3, w4, w5, w6, w7, w8, out, n);
    } else {
        pee_kernel<true><<<blocks, 256>>>(x, w1, w2, w3, w4, w5, w6, w7, w8, out, n);
    }
}